// round 8
// baseline (speedup 1.0000x reference)
#include <cuda_runtime.h>
#include <cstdint>

#define NMAX 50000
#define EMAX 1600000
#define HC   64
#define NEG_SLOPE 0.2f

// ---------------- device scratch (no allocation allowed) ----------------
__device__ float g_xl [NMAX * HC];
__device__ float g_xr [NMAX * HC];
__device__ float g_h  [NMAX * HC];
__device__ int   g_deg[NMAX];
__device__ int   g_off[NMAX + 1];
__device__ int   g_pos[NMAX];
__device__ int   g_csr_src[EMAX];
__device__ int   g_is64;

__device__ __forceinline__ float lrelu(float v) {
    return v > 0.f ? v : NEG_SLOPE * v;
}

__device__ __forceinline__ uint32_t tf32_round(float x) {
    uint32_t r;
    asm("cvt.rna.tf32.f32 %0, %1;" : "=r"(r) : "f"(x));
    return r;
}

// ---------------- edge_index dtype detection ------------------------------
__global__ void detect_dtype_kernel(const int* __restrict__ w) {
    if (threadIdx.x == 0 && blockIdx.x == 0) {
        int any = 0;
        for (int i = 0; i < 64; i++) any |= w[2 * i + 1];
        g_is64 = (any == 0) ? 1 : 0;
    }
}
__device__ __forceinline__ int load_idx(const void* ei, int i) {
    return g_is64 ? (int)((const long long*)ei)[i] : ((const int*)ei)[i];
}

// ---------------- CSR build (4 edges/thread) ------------------------------
__global__ void hist_kernel(const void* __restrict__ ei, int E) {
    int base = (blockIdx.x * blockDim.x + threadIdx.x) * 4;
    if (base >= E) return;
    int n = E - base; if (n > 4) n = 4;
    int d[4];
#pragma unroll
    for (int j = 0; j < 4; j++)
        if (j < n) d[j] = load_idx(ei, base + j + E);
#pragma unroll
    for (int j = 0; j < 4; j++)
        if (j < n) atomicAdd(&g_deg[d[j]], 1);
}

__global__ void __launch_bounds__(1024) scan_kernel(int N) {
    __shared__ int part[1024];
    int t = threadIdx.x;
    int chunk = (N + 1023) >> 10;
    int b = t * chunk; if (b > N) b = N;
    int e = b + chunk; if (e > N) e = N;
    int s = 0;
    for (int i = b; i < e; i++) s += g_deg[i];
    part[t] = s;
    __syncthreads();
    for (int d = 1; d < 1024; d <<= 1) {
        int v = (t >= d) ? part[t - d] : 0;
        __syncthreads();
        part[t] += v;
        __syncthreads();
    }
    int run = (t == 0) ? 0 : part[t - 1];
    for (int i = b; i < e; i++) {
        g_off[i] = run;
        g_pos[i] = run;
        run += g_deg[i];
    }
    if (e == N) g_off[N] = run;
}

__global__ void scatter_kernel(const void* __restrict__ ei, int E) {
    int base = (blockIdx.x * blockDim.x + threadIdx.x) * 4;
    if (base >= E) return;
    int n = E - base; if (n > 4) n = 4;
    int s[4], d[4];
#pragma unroll
    for (int j = 0; j < 4; j++)
        if (j < n) { s[j] = load_idx(ei, base + j); d[j] = load_idx(ei, base + j + E); }
    int slot[4];
#pragma unroll
    for (int j = 0; j < 4; j++)
        if (j < n) slot[j] = atomicAdd(&g_pos[d[j]], 1);
#pragma unroll
    for (int j = 0; j < 4; j++)
        if (j < n) g_csr_src[slot[j]] = s[j];
}

// ---------------- split-tf32 mma.sync GEMM (vectorized frag loads) --------
// C[z][M,NC] = A[M,K] @ W[z][K,NC] + bias[z]; fp32-accurate via
// AhiBhi + AhiBlo + AloBhi. CTA tile 128x64, 8 warps (4M x 2N, 32x32 each),
// K-chunk 32, mma.sync.m16n8k8 tf32.
//
// A smem layout (per hi/lo): [row 0..127][k'] stride 36 words, where
//   k' = (k&3)*8 + (k&4) + (k>>3)  (k = q*8 + b*4 + t)
// so a lane's fragments for all 4 q at fixed (row, b) are one float4 at
// word row*36 + t*8 + b*4.
//
// B smem layout (per hi/lo): word = row'*64 + (n' ^ (s<<3)), where
//   row' = q*8 + t*2 + b, s = row'&7 = (2t+b)&7, n' = ((n&7)<<3)|(n>>3)
// so a lane's fragments for all 4 j at fixed (q,b) are one float4 at
// word row'*64 + ((g^s)<<3) + wn*4.
#define ASTRIDE 36
#define A_WORDS (128 * ASTRIDE)          // 4608
#define B_WORDS (32 * 64)                // 2048
#define SM_FLOATS (2 * A_WORDS + 2 * B_WORDS)   // 13312
#define SM_BYTES  (SM_FLOATS * 4)               // 53248

__device__ __forceinline__ void mma8(float* c, const uint32_t* a, const uint32_t* b) {
    asm volatile(
        "mma.sync.aligned.m16n8k8.row.col.f32.tf32.tf32.f32 "
        "{%0,%1,%2,%3}, {%4,%5,%6,%7}, {%8,%9}, {%0,%1,%2,%3};"
        : "+f"(c[0]), "+f"(c[1]), "+f"(c[2]), "+f"(c[3])
        : "r"(a[0]), "r"(a[1]), "r"(a[2]), "r"(a[3]), "r"(b[0]), "r"(b[1]));
}

template<int ACT>  // 0 = none, 1 = sigmoid
__global__ void __launch_bounds__(256) mma_gemm_kernel(
    const float* __restrict__ A,
    const float* __restrict__ W0, const float* __restrict__ b0, float* __restrict__ C0,
    const float* __restrict__ W1, const float* __restrict__ b1, float* __restrict__ C1,
    int M, int K, int NC)
{
    const float* W    = blockIdx.z ? W1 : W0;
    const float* bias = blockIdx.z ? b1 : b0;
    float*       C    = blockIdx.z ? C1 : C0;

    extern __shared__ float sm[];
    float* Ahi = sm;
    float* Alo = sm + A_WORDS;
    float* Bhi = sm + 2 * A_WORDS;
    float* Blo = Bhi + B_WORDS;

    const int tid = threadIdx.x;
    const int wid = tid >> 5;
    const int lid = tid & 31;
    const int t   = lid & 3;      // threadID_in_group
    const int g   = lid >> 2;     // groupID
    const int wm  = wid & 3;      // warp M index (0..3)
    const int wn  = wid >> 2;     // warp N index (0..1)
    const int bm  = blockIdx.x * 128;
    const int bn  = blockIdx.y * 64;

    float acc[2][4][4];
#pragma unroll
    for (int i = 0; i < 2; i++)
#pragma unroll
        for (int j = 0; j < 4; j++)
#pragma unroll
            for (int q = 0; q < 4; q++) acc[i][j][q] = 0.f;

    for (int kk = 0; kk < K; kk += 32) {
        // ---- fill A chunk: 128 rows x 32 k, permuted k' layout ----
#pragma unroll
        for (int it = 0; it < 4; it++) {
            int idx = tid + it * 256;          // 0..1023 float4 slots
            int row = idx >> 3;
            int c4  = (idx & 7) * 4;
            float4 v = make_float4(0.f, 0.f, 0.f, 0.f);
            if (bm + row < M)
                v = *(const float4*)(A + (size_t)(bm + row) * K + kk + c4);
            float vv[4] = {v.x, v.y, v.z, v.w};
#pragma unroll
            for (int j = 0; j < 4; j++) {
                int k  = c4 + j;
                int kp = (k & 3) * 8 + (k & 4) + (k >> 3);
                uint32_t hb = tf32_round(vv[j]);
                float hf = __uint_as_float(hb);
                uint32_t lb = tf32_round(vv[j] - hf);
                Ahi[row * ASTRIDE + kp] = hf;
                Alo[row * ASTRIDE + kp] = __uint_as_float(lb);
            }
        }
        // ---- fill B chunk: 32 k x 64 n, permuted row'/n' layout ----
#pragma unroll
        for (int it = 0; it < 2; it++) {
            int idx = tid + it * 256;          // 0..511 float4 slots
            int kr  = idx >> 4;
            int cw  = (idx & 15) * 4;
            float4 v = *(const float4*)(W + (size_t)(kk + kr) * NC + bn + cw);
            int rowp = (kr >> 3) * 8 + (kr & 3) * 2 + ((kr >> 2) & 1);
            int s    = rowp & 7;
            float vv[4] = {v.x, v.y, v.z, v.w};
#pragma unroll
            for (int j = 0; j < 4; j++) {
                int n  = cw + j;
                int np = (((n & 7) << 3) | (n >> 3)) ^ (s << 3);
                uint32_t hb = tf32_round(vv[j]);
                float hf = __uint_as_float(hb);
                uint32_t lb = tf32_round(vv[j] - hf);
                Bhi[rowp * 64 + np] = hf;
                Blo[rowp * 64 + np] = __uint_as_float(lb);
            }
        }
        __syncthreads();

        // ---- phase 1: Ahi x (Bhi + Blo) ----
        uint32_t af[2][2][2][4];   // [i][rowsel][b][q]
#pragma unroll
        for (int i = 0; i < 2; i++)
#pragma unroll
            for (int r = 0; r < 2; r++)
#pragma unroll
                for (int b = 0; b < 2; b++) {
                    int row = wm * 32 + i * 16 + g + r * 8;
                    uint4 v = *(const uint4*)(Ahi + row * ASTRIDE + t * 8 + b * 4);
                    af[i][r][b][0] = v.x; af[i][r][b][1] = v.y;
                    af[i][r][b][2] = v.z; af[i][r][b][3] = v.w;
                }
#pragma unroll
        for (int q = 0; q < 4; q++) {
            uint32_t bh[2][4], bl[2][4];
#pragma unroll
            for (int b = 0; b < 2; b++) {
                int rowp = q * 8 + t * 2 + b;
                int s    = rowp & 7;
                int off  = rowp * 64 + ((g ^ s) << 3) + wn * 4;
                uint4 vh = *(const uint4*)(Bhi + off);
                uint4 vl = *(const uint4*)(Blo + off);
                bh[b][0] = vh.x; bh[b][1] = vh.y; bh[b][2] = vh.z; bh[b][3] = vh.w;
                bl[b][0] = vl.x; bl[b][1] = vl.y; bl[b][2] = vl.z; bl[b][3] = vl.w;
            }
#pragma unroll
            for (int i = 0; i < 2; i++) {
                uint32_t a[4] = {af[i][0][0][q], af[i][1][0][q],
                                 af[i][0][1][q], af[i][1][1][q]};
#pragma unroll
                for (int j = 0; j < 4; j++) {
                    uint32_t bb[2] = {bh[0][j], bh[1][j]};
                    mma8(acc[i][j], a, bb);
                    uint32_t bb2[2] = {bl[0][j], bl[1][j]};
                    mma8(acc[i][j], a, bb2);
                }
            }
        }

        // ---- phase 2: Alo x Bhi ----
#pragma unroll
        for (int i = 0; i < 2; i++)
#pragma unroll
            for (int r = 0; r < 2; r++)
#pragma unroll
                for (int b = 0; b < 2; b++) {
                    int row = wm * 32 + i * 16 + g + r * 8;
                    uint4 v = *(const uint4*)(Alo + row * ASTRIDE + t * 8 + b * 4);
                    af[i][r][b][0] = v.x; af[i][r][b][1] = v.y;
                    af[i][r][b][2] = v.z; af[i][r][b][3] = v.w;
                }
#pragma unroll
        for (int q = 0; q < 4; q++) {
            uint32_t bh[2][4];
#pragma unroll
            for (int b = 0; b < 2; b++) {
                int rowp = q * 8 + t * 2 + b;
                int s    = rowp & 7;
                int off  = rowp * 64 + ((g ^ s) << 3) + wn * 4;
                uint4 vh = *(const uint4*)(Bhi + off);
                bh[b][0] = vh.x; bh[b][1] = vh.y; bh[b][2] = vh.z; bh[b][3] = vh.w;
            }
#pragma unroll
            for (int i = 0; i < 2; i++) {
                uint32_t a[4] = {af[i][0][0][q], af[i][1][0][q],
                                 af[i][0][1][q], af[i][1][1][q]};
#pragma unroll
                for (int j = 0; j < 4; j++) {
                    uint32_t bb[2] = {bh[0][j], bh[1][j]};
                    mma8(acc[i][j], a, bb);
                }
            }
        }
        __syncthreads();
    }

    // ---- epilogue ----
#pragma unroll
    for (int i = 0; i < 2; i++) {
        int r0 = bm + wm * 32 + i * 16 + g;
#pragma unroll
        for (int j = 0; j < 4; j++) {
            int col = bn + wn * 32 + j * 8 + 2 * t;
            float bz0 = bias[col], bz1 = bias[col + 1];
            float v0 = acc[i][j][0] + bz0;
            float v1 = acc[i][j][1] + bz1;
            float v2 = acc[i][j][2] + bz0;
            float v3 = acc[i][j][3] + bz1;
            if (ACT == 1) {
                v0 = 1.f / (1.f + __expf(-v0));
                v1 = 1.f / (1.f + __expf(-v1));
                v2 = 1.f / (1.f + __expf(-v2));
                v3 = 1.f / (1.f + __expf(-v3));
            }
            if (r0 < M)
                *(float2*)(C + (size_t)r0 * NC + col) = make_float2(v0, v1);
            if (r0 + 8 < M)
                *(float2*)(C + (size_t)(r0 + 8) * NC + col) = make_float2(v2, v3);
        }
    }
}

// ---------------- fused per-node GATv2 aggregation ------------------------
__device__ __forceinline__ void gat_edge_step(
    float2 xv, float2 xrv, float a0, float a1,
    float& accx, float& accy, float& den)
{
    float p = a0 * lrelu(xv.x + xrv.x) + a1 * lrelu(xv.y + xrv.y);
    p += __shfl_xor_sync(0xffffffffu, p, 1);
    p += __shfl_xor_sync(0xffffffffu, p, 2);
    p += __shfl_xor_sync(0xffffffffu, p, 4);
    float ex = __expf(p);
    den  += ex;
    accx += ex * xv.x;
    accy += ex * xv.y;
}

__global__ void __launch_bounds__(256) gat_aggregate_kernel(
    const float* __restrict__ xl, const float* __restrict__ xr,
    const float* __restrict__ att, const float* __restrict__ bias,
    float* __restrict__ out, int N)
{
    int warp = (blockIdx.x * blockDim.x + threadIdx.x) >> 5;
    int c    = threadIdx.x & 31;
    if (warp >= N) return;
    const int d = warp;

    const float a0 = att[2 * c];
    const float a1 = att[2 * c + 1];
    const float2 xrv = *(const float2*)(xr + (size_t)d * 64 + 2 * c);

    const int beg = g_off[d];
    const int end = g_off[d + 1];

    float accx = 0.f, accy = 0.f, den = 0.f;

    for (int i = beg; i < end; ) {
        int cnt = end - i;
        if (cnt > 32) cnt = 32;
        int my_src = (c < cnt) ? g_csr_src[i + c] : 0;

        int j = 0;
        for (; j + 4 <= cnt; j += 4) {
            int s0 = __shfl_sync(0xffffffffu, my_src, j);
            int s1 = __shfl_sync(0xffffffffu, my_src, j + 1);
            int s2 = __shfl_sync(0xffffffffu, my_src, j + 2);
            int s3 = __shfl_sync(0xffffffffu, my_src, j + 3);
            float2 v0 = *(const float2*)(xl + (size_t)s0 * 64 + 2 * c);
            float2 v1 = *(const float2*)(xl + (size_t)s1 * 64 + 2 * c);
            float2 v2 = *(const float2*)(xl + (size_t)s2 * 64 + 2 * c);
            float2 v3 = *(const float2*)(xl + (size_t)s3 * 64 + 2 * c);
            gat_edge_step(v0, xrv, a0, a1, accx, accy, den);
            gat_edge_step(v1, xrv, a0, a1, accx, accy, den);
            gat_edge_step(v2, xrv, a0, a1, accx, accy, den);
            gat_edge_step(v3, xrv, a0, a1, accx, accy, den);
        }
        for (; j < cnt; j++) {
            int s = __shfl_sync(0xffffffffu, my_src, j);
            float2 v = *(const float2*)(xl + (size_t)s * 64 + 2 * c);
            gat_edge_step(v, xrv, a0, a1, accx, accy, den);
        }
        i += cnt;
    }

    float inv = (den > 0.f) ? (1.f / den) : 0.f;
    float ox = fmaxf(accx * inv + bias[2 * c],     0.f);
    float oy = fmaxf(accy * inv + bias[2 * c + 1], 0.f);
    *(float2*)(out + (size_t)d * 64 + 2 * c) = make_float2(ox, oy);
}

// ---------------- launch --------------------------------------------------
extern "C" void kernel_launch(void* const* d_in, const int* in_sizes, int n_in,
                              void* d_out, int out_size)
{
    const float* x    = (const float*)d_in[0];
    const void*  ei   = d_in[1];
    const float* Wl1  = (const float*)d_in[2];
    const float* bl1  = (const float*)d_in[3];
    const float* Wr1  = (const float*)d_in[4];
    const float* br1  = (const float*)d_in[5];
    const float* att1 = (const float*)d_in[6];
    const float* bias1= (const float*)d_in[7];
    const float* Wl2  = (const float*)d_in[8];
    const float* bl2  = (const float*)d_in[9];
    const float* Wr2  = (const float*)d_in[10];
    const float* br2  = (const float*)d_in[11];
    const float* att2 = (const float*)d_in[12];
    const float* bias2= (const float*)d_in[13];
    const float* Wo   = (const float*)d_in[14];
    const float* bo   = (const float*)d_in[15];

    const int Nn = in_sizes[0] / 256;      // 50000
    const int E  = in_sizes[1] / 2;        // 1600000

    float *p_xl, *p_xr, *p_h;
    int *p_deg;
    cudaGetSymbolAddress((void**)&p_xl,  g_xl);
    cudaGetSymbolAddress((void**)&p_xr,  g_xr);
    cudaGetSymbolAddress((void**)&p_h,   g_h);
    cudaGetSymbolAddress((void**)&p_deg, g_deg);

    static cudaStream_t s_csr = nullptr;
    static cudaEvent_t  ev_fork = nullptr, ev_join = nullptr;
    if (s_csr == nullptr) {
        cudaStreamCreateWithFlags(&s_csr, cudaStreamNonBlocking);
        cudaEventCreateWithFlags(&ev_fork, cudaEventDisableTiming);
        cudaEventCreateWithFlags(&ev_join, cudaEventDisableTiming);
        cudaFuncSetAttribute(mma_gemm_kernel<0>,
                             cudaFuncAttributeMaxDynamicSharedMemorySize, SM_BYTES);
        cudaFuncSetAttribute(mma_gemm_kernel<1>,
                             cudaFuncAttributeMaxDynamicSharedMemorySize, SM_BYTES);
    }

    const int gm = (Nn + 127) / 128;       // 391
    const int eb4 = (E / 4 + 255) / 256;
    const int agb = (Nn * 32 + 255) / 256;

    // ---- fork: CSR build on side stream, concurrent with layer-1 GEMM ----
    cudaEventRecord(ev_fork, 0);
    cudaStreamWaitEvent(s_csr, ev_fork, 0);

    detect_dtype_kernel<<<1, 32, 0, s_csr>>>((const int*)ei);
    cudaMemsetAsync(p_deg, 0, (size_t)Nn * sizeof(int), s_csr);
    hist_kernel<<<eb4, 256, 0, s_csr>>>(ei, E);
    scan_kernel<<<1, 1024, 0, s_csr>>>(Nn);
    scatter_kernel<<<eb4, 256, 0, s_csr>>>(ei, E);
    cudaEventRecord(ev_join, s_csr);

    // ---- layer 1 GEMMs (tensor via mma.sync) ----
    mma_gemm_kernel<0><<<dim3(gm, 1, 2), 256, SM_BYTES>>>(
        x, Wl1, bl1, p_xl, Wr1, br1, p_xr, Nn, 256, 64);

    cudaStreamWaitEvent(0, ev_join, 0);
    gat_aggregate_kernel<<<agb, 256>>>(p_xl, p_xr, att1, bias1, p_h, Nn);

    // ---- layer 2 ----
    mma_gemm_kernel<0><<<dim3(gm, 1, 2), 256, SM_BYTES>>>(
        p_h, Wl2, bl2, p_xl, Wr2, br2, p_xr, Nn, 64, 64);
    gat_aggregate_kernel<<<agb, 256>>>(p_xl, p_xr, att2, bias2, p_h, Nn);

    // ---- output head: sigmoid(h @ Wo + bo) -> d_out ----
    mma_gemm_kernel<1><<<dim3(gm, 4, 1), 256, SM_BYTES>>>(
        p_h, Wo, bo, (float*)d_out, Wo, bo, (float*)d_out, Nn, 64, 256);
}